// round 15
// baseline (speedup 1.0000x reference)
#include <cuda_runtime.h>
#include <cstdint>

// MeanAggregator: single-pass dense gather, final champion engine.
// out[b,:] = mean_k table[neighs[b,k],:], B=50000, K=32, table 500000x128 f32.
//
// One warp per node, short-lived 128-thread CTAs (scheduler overlaps draining
// warps with fresh CTAs' index loads). Lane = (half, sub): half = neighbor
// parity, sub = 32B slice of the 512B row. 16 paired 256-bit evict_last
// gathers, unrolled by 8 (8 loads front-batched per burst, ~4KB in flight per
// warp); fold halves with shfl_xor(16); lanes 0-15 stream-store the row.
//
// Measured: ~6.4TB/s on ~592MB irreducible traffic = 80% of HBM spec, the
// achieved ceiling for scattered 512B requests on this chip. L2 temporal
// blocking was tried in 6 variants (R5-R11): it halves DRAM traffic per pass
// but the per-pass engines are latency-bound at <40% BW -> strictly worse.

#define BATCH   50000
#define DEGREE  32
#define D_FEAT  128
#define WARPS_PER_BLOCK 4
#define THREADS (WARPS_PER_BLOCK * 32)
#define FULL    0xffffffffu

struct F8 { float v[8]; };

__device__ __forceinline__ F8 ldg_evict_last_v8(const float* p)
{
    F8 r;
    asm volatile(
        "ld.global.nc.L2::evict_last.v8.b32 {%0,%1,%2,%3,%4,%5,%6,%7}, [%8];"
        : "=f"(r.v[0]), "=f"(r.v[1]), "=f"(r.v[2]), "=f"(r.v[3]),
          "=f"(r.v[4]), "=f"(r.v[5]), "=f"(r.v[6]), "=f"(r.v[7])
        : "l"(p));
    return r;
}

__device__ __forceinline__ void stg_streaming_v4(float4* p, float4 v)
{
    asm volatile("st.global.cs.v4.f32 [%0], {%1,%2,%3,%4};"
                 :: "l"(p), "f"(v.x), "f"(v.y), "f"(v.z), "f"(v.w)
                 : "memory");
}

__global__ __launch_bounds__(THREADS)
void mean_agg_kernel(const void* __restrict__ neighs_raw,
                     const float* __restrict__ table,   // [500000, 128] f32
                     float4* __restrict__ out)          // [50000, 32] float4
{
    const int warp = (blockIdx.x * THREADS + threadIdx.x) >> 5;
    const int lane = threadIdx.x & 31;
    if (warp >= BATCH) return;

    const int half = lane >> 4;   // neighbor parity this lane serves
    const int sub  = lane & 15;   // 32B slice of the 512B row

    // Inline dtype detection: int64 indices in [0,500000) have zero odd 32-bit
    // words; int32 data has random indices there (P(4 zeros) ~ 1.6e-23).
    // One hot cache line for the whole grid -> broadcast hit.
    const unsigned* n32 = (const unsigned*)neighs_raw;
    const bool is64 = ((n32[1] | n32[3] | n32[5] | n32[7]) == 0u);

    // One coalesced streaming load of this node's 32 indices (lane k -> idx k).
    int my_idx;
    if (is64) {
        my_idx = (int)__ldcs(&((const long long*)neighs_raw)
                             [(size_t)warp * DEGREE + lane]);
    } else {
        my_idx = __ldcs(&((const int*)neighs_raw)
                        [(size_t)warp * DEGREE + lane]);
    }

    float acc[8] = {0.f, 0.f, 0.f, 0.f, 0.f, 0.f, 0.f, 0.f};

    // 16 paired gathers, unrolled by 8: 8 independent loads per burst.
    #pragma unroll 8
    for (int k = 0; k < DEGREE / 2; ++k) {
        const int idx = __shfl_sync(FULL, my_idx, 2 * k + half);
        const F8 r = ldg_evict_last_v8(&table[(size_t)idx * D_FEAT + sub * 8]);
        #pragma unroll
        for (int i = 0; i < 8; ++i) acc[i] += r.v[i];
    }

    // Fold halves: lanes l and l^16 hold the same columns, disjoint k-sets.
    #pragma unroll
    for (int i = 0; i < 8; ++i)
        acc[i] += __shfl_xor_sync(FULL, acc[i], 16);

    if (half == 0) {
        const float s = 1.0f / (float)DEGREE;
        float4 lo = make_float4(acc[0] * s, acc[1] * s, acc[2] * s, acc[3] * s);
        float4 hi = make_float4(acc[4] * s, acc[5] * s, acc[6] * s, acc[7] * s);
        float4* dst = &out[(size_t)warp * (D_FEAT / 4) + sub * 2];
        stg_streaming_v4(dst, lo);
        stg_streaming_v4(dst + 1, hi);
    }
}

extern "C" void kernel_launch(void* const* d_in, const int* in_sizes, int n_in,
                              void* d_out, int out_size)
{
    const void*  neighs = d_in[0];
    const float* table  = (const float*)d_in[1];
    float4*      out    = (float4*)d_out;

    const int blocks = (BATCH + WARPS_PER_BLOCK - 1) / WARPS_PER_BLOCK;
    mean_agg_kernel<<<blocks, THREADS>>>(neighs, table, out);
}

// round 16
// speedup vs baseline: 1.0270x; 1.0270x over previous
#include <cuda_runtime.h>
#include <cstdint>

// MeanAggregator: single-pass dense gather — FINAL champion (R14 config).
// out[b,:] = mean_k table[neighs[b,k],:], B=50000, K=32, table 500000x128 f32.
//
// One warp per node, short-lived 128-thread CTAs (scheduler overlaps draining
// warps with fresh CTAs' index loads — measured 13% faster than persistent
// grid-stride). Lane = (half, sub): half = neighbor parity, sub = 32B slice of
// the 512B row. 16 fully-unrolled paired 256-bit evict_last gathers (regs=32,
// occ ~91%); fold halves with shfl_xor(16); lanes 0-15 stream-store the row.
//
// Why this is the floor: ~592MB irreducible DRAM traffic at ~6.3-6.4TB/s
// (80% of HBM spec — the achieved ceiling for scattered 512B requests).
// L2 temporal blocking (6 engine variants, R5-R11) halves per-pass traffic
// but is latency-bound at <40% BW -> strictly worse. Tensor/TMA inapplicable.

#define BATCH   50000
#define DEGREE  32
#define D_FEAT  128
#define WARPS_PER_BLOCK 4
#define THREADS (WARPS_PER_BLOCK * 32)
#define FULL    0xffffffffu

struct F8 { float v[8]; };

__device__ __forceinline__ F8 ldg_evict_last_v8(const float* p)
{
    F8 r;
    asm volatile(
        "ld.global.nc.L2::evict_last.v8.b32 {%0,%1,%2,%3,%4,%5,%6,%7}, [%8];"
        : "=f"(r.v[0]), "=f"(r.v[1]), "=f"(r.v[2]), "=f"(r.v[3]),
          "=f"(r.v[4]), "=f"(r.v[5]), "=f"(r.v[6]), "=f"(r.v[7])
        : "l"(p));
    return r;
}

__device__ __forceinline__ void stg_streaming_v4(float4* p, float4 v)
{
    asm volatile("st.global.cs.v4.f32 [%0], {%1,%2,%3,%4};"
                 :: "l"(p), "f"(v.x), "f"(v.y), "f"(v.z), "f"(v.w)
                 : "memory");
}

__global__ __launch_bounds__(THREADS)
void mean_agg_kernel(const void* __restrict__ neighs_raw,
                     const float* __restrict__ table,   // [500000, 128] f32
                     float4* __restrict__ out)          // [50000, 32] float4
{
    const int warp = (blockIdx.x * THREADS + threadIdx.x) >> 5;
    const int lane = threadIdx.x & 31;
    if (warp >= BATCH) return;

    const int half = lane >> 4;   // neighbor parity this lane serves
    const int sub  = lane & 15;   // 32B slice of the 512B row

    // Inline dtype detection: int64 indices in [0,500000) have zero odd 32-bit
    // words; int32 data has random indices there (P(4 zeros) ~ 1.6e-23).
    // One hot cache line for the whole grid -> broadcast hit.
    const unsigned* n32 = (const unsigned*)neighs_raw;
    const bool is64 = ((n32[1] | n32[3] | n32[5] | n32[7]) == 0u);

    // One coalesced streaming load of this node's 32 indices (lane k -> idx k).
    int my_idx;
    if (is64) {
        my_idx = (int)__ldcs(&((const long long*)neighs_raw)
                             [(size_t)warp * DEGREE + lane]);
    } else {
        my_idx = __ldcs(&((const int*)neighs_raw)
                        [(size_t)warp * DEGREE + lane]);
    }

    float acc[8] = {0.f, 0.f, 0.f, 0.f, 0.f, 0.f, 0.f, 0.f};

    // Fully unrolled: 16 independent paired gathers, maximal front-batching.
    #pragma unroll
    for (int k = 0; k < DEGREE / 2; ++k) {
        const int idx = __shfl_sync(FULL, my_idx, 2 * k + half);
        const F8 r = ldg_evict_last_v8(&table[(size_t)idx * D_FEAT + sub * 8]);
        #pragma unroll
        for (int i = 0; i < 8; ++i) acc[i] += r.v[i];
    }

    // Fold halves: lanes l and l^16 hold the same columns, disjoint k-sets.
    #pragma unroll
    for (int i = 0; i < 8; ++i)
        acc[i] += __shfl_xor_sync(FULL, acc[i], 16);

    if (half == 0) {
        const float s = 1.0f / (float)DEGREE;
        float4 lo = make_float4(acc[0] * s, acc[1] * s, acc[2] * s, acc[3] * s);
        float4 hi = make_float4(acc[4] * s, acc[5] * s, acc[6] * s, acc[7] * s);
        float4* dst = &out[(size_t)warp * (D_FEAT / 4) + sub * 2];
        stg_streaming_v4(dst, lo);
        stg_streaming_v4(dst + 1, hi);
    }
}

extern "C" void kernel_launch(void* const* d_in, const int* in_sizes, int n_in,
                              void* d_out, int out_size)
{
    const void*  neighs = d_in[0];
    const float* table  = (const float*)d_in[1];
    float4*      out    = (float4*)d_out;

    const int blocks = (BATCH + WARPS_PER_BLOCK - 1) / WARPS_PER_BLOCK;
    mean_agg_kernel<<<blocks, THREADS>>>(neighs, table, out);
}